// round 11
// baseline (speedup 1.0000x reference)
#include <cuda_runtime.h>
#include <cuda_bf16.h>
#include <stdint.h>

#define BG    8      // graphs
#define NPER  256    // nodes per graph
#define NN    2048   // total nodes
#define FF    512    // features
#define EE    65536  // edges
#define KSEL  204    // kept per graph
#define NK    1632   // pooled nodes
#define KHOP  3

#define OUT_FEATP_OFF 0
#define OUT_W_OFF     (NK*FF)                 // 835584
#define OUT_PERM_OFF  (NK*FF + NK*NK)         // 3499008

// tf32 helpers ------------------------------------------------------------
__device__ __forceinline__ uint32_t to_tf32(float x) {
    uint32_t h;
    asm("cvt.rna.tf32.f32 %0, %1;" : "=r"(h) : "f"(x));
    return h;
}
__device__ __forceinline__ void split_tf32(float x, uint32_t& hi, uint32_t& lo) {
    hi = to_tf32(x);
    float l = x - __uint_as_float(hi);
    lo = to_tf32(l);
}
#define MMA8(D,A,B) \
    asm("mma.sync.aligned.m16n8k8.row.col.f32.tf32.tf32.f32 " \
        "{%0,%1,%2,%3},{%4,%5,%6,%7},{%8,%9},{%0,%1,%2,%3};" \
        : "+f"(D[0]), "+f"(D[1]), "+f"(D[2]), "+f"(D[3]) \
        : "r"(A[0]), "r"(A[1]), "r"(A[2]), "r"(A[3]), "r"(B[0]), "r"(B[1]))

// ---------------- scratch (device globals; no allocation allowed) ----------
__device__ float  d_A[BG*NPER*NPER];    // original adjacency (read-only post-scatter)
__device__ float  d_T0[BG*NPER*NPER];   // hop-1 product
__device__ float  d_T1[BG*NPER*NPER];   // hop-2 product
__device__ float  d_T2[BG*NPER*NPER];   // hop-3 product
__device__ float  d_AGG[4*NN*FF];       // 4 k-split partials of agg
__device__ float  d_deg_out[NN];
__device__ float  d_deg_in[NN];
__device__ double d_score[NN];          // double: top-k rank must match truth
__device__ int    d_perm_local[BG*KSEL];
__device__ float  d_ssrc[NK];
__device__ float  d_sdst[NK];
__device__ float  d_maxT[KHOP];

// ---------------- init ---------------------------------------------------
__global__ void k_init(float* out) {
    int64_t i = (int64_t)blockIdx.x * blockDim.x + threadIdx.x;
    int64_t stride = (int64_t)gridDim.x * blockDim.x;
    float* w = out + OUT_W_OFF;
    for (int64_t t = i; t < (int64_t)NK*NK; t += stride) w[t] = 0.0f;
    for (int64_t t = i; t < (int64_t)BG*NPER*NPER; t += stride) d_A[t] = 0.0f;
    for (int64_t t = i; t < NN; t += stride) {
        d_deg_out[t] = 0.0f; d_deg_in[t] = 0.0f;
    }
    if (i < KHOP) d_maxT[i] = 0.0f;
}

// ---------------- scatter edges + degrees --------------------------------
__global__ void k_scatter(const float* __restrict__ ef,
                          const int* __restrict__ row,
                          const int* __restrict__ col) {
    int e = blockIdx.x * blockDim.x + threadIdx.x;
    if (e >= EE) return;
    int r = row[e], c = col[e];
    int g = r >> 8;
    atomicAdd(&d_A[(g << 16) + ((r & 255) << 8) + (c & 255)], ef[e]);
    atomicAdd(&d_deg_out[r], 1.0f);
    atomicAdd(&d_deg_in[c], 1.0f);
}

// ------- partial agg = (sym-norm A^T)[k-quarter] @ feat (3xTF32) ----------
// grid (FF/64, NPER/64, BG*4), block 256. 64x64 tile, warps 2(m)x4(n).
__global__ void __launch_bounds__(256) k_agg_mma(const float* __restrict__ feat) {
    const int g = blockIdx.z >> 2;
    const int split = blockIdx.z & 3;
    const int fBase = blockIdx.x * 64;
    const int cBase = blockIdx.y * 64;
    const int tid = threadIdx.x, lane = tid & 31, wid = tid >> 5;
    const int wm = (wid & 1) * 32, wn = (wid >> 1) * 16;
    __shared__ float As[64][33];   // [m=c_local][k]
    __shared__ float Bs[64][33];   // [n=f_local][k]
    const float* Ag = d_A + (g << 16);
    const float* fg = feat + (g << 17);
    const int splitOff = split * 64;

    float acc[2][2][4] = {};

    const int kl = tid >> 4;          // 0..15
    const int m4 = (tid & 15) * 4;

    for (int s = 0; s < 2; s++) {
        const int kOff = splitOff + s * 32;
        __syncthreads();
        #pragma unroll
        for (int it = 0; it < 2; it++) {
            int k = kl + it * 16;
            int kG = kOff + k;
            float sc = 1.0f / sqrtf(fmaxf(d_deg_out[(g << 8) + kG], 1.0f));
            float4 va = *(const float4*)(Ag + kG * 256 + cBase + m4);
            float4 vb = *(const float4*)(fg + kG * 512 + fBase + m4);
            int c0 = cBase + m4;
            As[m4 + 0][k] = (kG == c0 + 0) ? 0.0f : va.x * sc;
            As[m4 + 1][k] = (kG == c0 + 1) ? 0.0f : va.y * sc;
            As[m4 + 2][k] = (kG == c0 + 2) ? 0.0f : va.z * sc;
            As[m4 + 3][k] = (kG == c0 + 3) ? 0.0f : va.w * sc;
            Bs[m4 + 0][k] = vb.x;
            Bs[m4 + 1][k] = vb.y;
            Bs[m4 + 2][k] = vb.z;
            Bs[m4 + 3][k] = vb.w;
        }
        __syncthreads();
        #pragma unroll
        for (int k8 = 0; k8 < 4; k8++) {
            int kb = k8 * 8;
            uint32_t ah[2][4], al[2][4], bh[2][2], bl[2][2];
            #pragma unroll
            for (int mt = 0; mt < 2; mt++) {
                int r = wm + mt * 16 + (lane >> 2);
                split_tf32(As[r    ][kb + (lane & 3)    ], ah[mt][0], al[mt][0]);
                split_tf32(As[r + 8][kb + (lane & 3)    ], ah[mt][1], al[mt][1]);
                split_tf32(As[r    ][kb + (lane & 3) + 4], ah[mt][2], al[mt][2]);
                split_tf32(As[r + 8][kb + (lane & 3) + 4], ah[mt][3], al[mt][3]);
            }
            #pragma unroll
            for (int nt = 0; nt < 2; nt++) {
                int n = wn + nt * 8 + (lane >> 2);
                split_tf32(Bs[n][kb + (lane & 3)    ], bh[nt][0], bl[nt][0]);
                split_tf32(Bs[n][kb + (lane & 3) + 4], bh[nt][1], bl[nt][1]);
            }
            #pragma unroll
            for (int mt = 0; mt < 2; mt++)
                #pragma unroll
                for (int nt = 0; nt < 2; nt++) {
                    MMA8(acc[mt][nt], al[mt], bh[nt]);
                    MMA8(acc[mt][nt], ah[mt], bl[nt]);
                    MMA8(acc[mt][nt], ah[mt], bh[nt]);
                }
        }
    }
    float* dst = d_AGG + (int64_t)split * NN * FF + ((int64_t)g << 17);
    #pragma unroll
    for (int mt = 0; mt < 2; mt++)
        #pragma unroll
        for (int nt = 0; nt < 2; nt++) {
            int r0 = cBase + wm + mt * 16 + (lane >> 2);
            int c  = fBase + wn + nt * 8 + 2 * (lane & 3);
            *(float2*)(dst + (int64_t)r0 * 512 + c) =
                make_float2(acc[mt][nt][0], acc[mt][nt][1]);
            *(float2*)(dst + (int64_t)(r0 + 8) * 512 + c) =
                make_float2(acc[mt][nt][2], acc[mt][nt][3]);
        }
}

// ------- score[c] = sum_f |feat - dn*(p0+p1+p2+p3)| (double), 1 warp/node -
__global__ void k_score(const float* __restrict__ feat) {
    int w = (blockIdx.x << 3) + (threadIdx.x >> 5);
    int lane = threadIdx.x & 31;
    const float* fr = feat + (int64_t)w * FF;
    const float* p0 = d_AGG + (int64_t)w * FF;
    const float* p1 = p0 + (int64_t)NN * FF;
    const float* p2 = p1 + (int64_t)NN * FF;
    const float* p3 = p2 + (int64_t)NN * FF;
    float dn = 1.0f / sqrtf(fmaxf(d_deg_in[w], 1.0f));
    double p = 0.0;
    #pragma unroll
    for (int it = 0; it < 4; it++) {
        int f = (it * 32 + lane) * 4;
        float4 fv = *(const float4*)(fr + f);
        float4 a0 = *(const float4*)(p0 + f);
        float4 a1 = *(const float4*)(p1 + f);
        float4 a2 = *(const float4*)(p2 + f);
        float4 a3 = *(const float4*)(p3 + f);
        p += (double)fabsf(fv.x - dn * (((a0.x + a1.x) + a2.x) + a3.x))
           + (double)fabsf(fv.y - dn * (((a0.y + a1.y) + a2.y) + a3.y))
           + (double)fabsf(fv.z - dn * (((a0.z + a1.z) + a2.z) + a3.z))
           + (double)fabsf(fv.w - dn * (((a0.w + a1.w) + a2.w) + a3.w));
    }
    #pragma unroll
    for (int off = 16; off > 0; off >>= 1)
        p += __shfl_down_sync(0xffffffffu, p, off);
    if (lane == 0) d_score[w] = p;
}

// ---------------- top-k per graph via bitonic sort (double keys) ----------
__global__ void k_topk(float* __restrict__ out_perm) {
    int g = blockIdx.x;
    int tid = threadIdx.x;
    __shared__ double sk[256];
    __shared__ int    si[256];
    sk[tid] = d_score[g*NPER + tid];
    si[tid] = tid;
    __syncthreads();
    for (int k2 = 2; k2 <= 256; k2 <<= 1) {
        for (int jj = k2 >> 1; jj > 0; jj >>= 1) {
            int ixj = tid ^ jj;
            if (ixj > tid) {
                double a = sk[tid], b = sk[ixj];
                int ia = si[tid], ib = si[ixj];
                bool aFirst = (a > b) || (a == b && ia < ib);
                bool desc = ((tid & k2) == 0);
                bool doswap = desc ? !aFirst : aFirst;
                if (doswap) { sk[tid] = b; sk[ixj] = a; si[tid] = ib; si[ixj] = ia; }
            }
            __syncthreads();
        }
    }
    if (tid < KSEL) {
        d_perm_local[g*KSEL + tid] = si[tid];
        out_perm[g*KSEL + tid] = (float)(g*NPER + si[tid]);
    }
}

// -------------- gather feat_p + attention scores --------------------------
__global__ void k_gather(const float* __restrict__ feat,
                         const float* __restrict__ att,
                         float* __restrict__ out_featp) {
    int i = blockIdx.x;
    int g = i / KSEL;
    int node = g*NPER + d_perm_local[i];
    int tid = threadIdx.x;
    const float* fr = feat + (int64_t)node * FF;
    float* orow = out_featp + (int64_t)i * FF;
    double a1 = 0.0, a2 = 0.0;
    for (int f = tid; f < FF; f += 128) {
        float v = fr[f];
        orow[f] = v;
        a1 += (double)v * (double)att[f];
        a2 += (double)v * (double)att[FF + f];
    }
    #pragma unroll
    for (int off = 16; off > 0; off >>= 1) {
        a1 += __shfl_down_sync(0xffffffffu, a1, off);
        a2 += __shfl_down_sync(0xffffffffu, a2, off);
    }
    __shared__ double s1[4], s2v[4];
    int w = tid >> 5, l = tid & 31;
    if (l == 0) { s1[w] = a1; s2v[w] = a2; }
    __syncthreads();
    if (tid == 0) {
        d_ssrc[i] = (float)(s1[0] + s1[1] + s1[2] + s1[3]);
        d_sdst[i] = (float)(s2v[0] + s2v[1] + s2v[2] + s2v[3]);
    }
}

// ---------------- khop: T_iter = Ain@Ain, Ain recomposed in-load ----------
// grid (4, 4, BG), block 256. Ain = A + s0*T0 (+ s1*T1) per iter.
__global__ void __launch_bounds__(256) k_mm(int iter) {
    const int g = blockIdx.z;
    const int cBase = blockIdx.x * 64;   // n
    const int rBase = blockIdx.y * 64;   // m
    const int tid = threadIdx.x, lane = tid & 31, wid = tid >> 5;
    const int wm = (wid & 1) * 32, wn = (wid >> 1) * 16;
    __shared__ float As[64][36];   // [m][k] (144B row stride: float4-aligned)
    __shared__ float Bs[64][33];   // [n][k]
    const int64_t gOff = (int64_t)g << 16;
    const float* Ag  = d_A  + gOff;
    const float* T0g = d_T0 + gOff;
    const float* T1g = d_T1 + gOff;
    float* Tout = (iter == 0 ? d_T0 : (iter == 1 ? d_T1 : d_T2)) + gOff;
    const float s0 = (iter >= 1) ? 1e-5f / d_maxT[0] : 0.0f;
    const float s1 = (iter >= 2) ? 1e-5f / d_maxT[1] : 0.0f;

    float acc[2][2][4] = {};

    const int mA = tid >> 2;                 // 0..63
    const int kA = (tid & 3) * 4;
    const int kB = tid >> 4;                 // 0..15
    const int n4 = (tid & 15) * 4;

    // load one float4 of the recomposed Ain at linear float offset 'off'
    auto ldin = [&](int off) -> float4 {
        float4 v = *(const float4*)(Ag + off);
        if (iter >= 1) {
            float4 t = *(const float4*)(T0g + off);
            v.x = fmaf(s0, t.x, v.x); v.y = fmaf(s0, t.y, v.y);
            v.z = fmaf(s0, t.z, v.z); v.w = fmaf(s0, t.w, v.w);
        }
        if (iter >= 2) {
            float4 t = *(const float4*)(T1g + off);
            v.x = fmaf(s1, t.x, v.x); v.y = fmaf(s1, t.y, v.y);
            v.z = fmaf(s1, t.z, v.z); v.w = fmaf(s1, t.w, v.w);
        }
        return v;
    };

    for (int s = 0; s < 8; s++) {
        const int kOff = s * 32;
        __syncthreads();
        #pragma unroll
        for (int it = 0; it < 2; it++) {
            int ka = kA + it * 16;
            float4 va = ldin((rBase + mA) * 256 + kOff + ka);
            *(float4*)&As[mA][ka] = va;
        }
        #pragma unroll
        for (int it = 0; it < 2; it++) {
            int k = kB + it * 16;
            int kG = kOff + k;
            float4 vb = ldin(kG * 256 + cBase + n4);
            Bs[n4 + 0][k] = vb.x;
            Bs[n4 + 1][k] = vb.y;
            Bs[n4 + 2][k] = vb.z;
            Bs[n4 + 3][k] = vb.w;
        }
        __syncthreads();
        #pragma unroll
        for (int k8 = 0; k8 < 4; k8++) {
            int kb = k8 * 8;
            uint32_t a[2][4], b[2][2];
            #pragma unroll
            for (int mt = 0; mt < 2; mt++) {
                int r = wm + mt * 16 + (lane >> 2);
                a[mt][0] = to_tf32(As[r    ][kb + (lane & 3)    ]);
                a[mt][1] = to_tf32(As[r + 8][kb + (lane & 3)    ]);
                a[mt][2] = to_tf32(As[r    ][kb + (lane & 3) + 4]);
                a[mt][3] = to_tf32(As[r + 8][kb + (lane & 3) + 4]);
            }
            #pragma unroll
            for (int nt = 0; nt < 2; nt++) {
                int n = wn + nt * 8 + (lane >> 2);
                b[nt][0] = to_tf32(Bs[n][kb + (lane & 3)    ]);
                b[nt][1] = to_tf32(Bs[n][kb + (lane & 3) + 4]);
            }
            #pragma unroll
            for (int mt = 0; mt < 2; mt++)
                #pragma unroll
                for (int nt = 0; nt < 2; nt++)
                    MMA8(acc[mt][nt], a[mt], b[nt]);
        }
    }
    float m = 0.0f;
    #pragma unroll
    for (int mt = 0; mt < 2; mt++)
        #pragma unroll
        for (int nt = 0; nt < 2; nt++) {
            int r0 = rBase + wm + mt * 16 + (lane >> 2);
            int c  = cBase + wn + nt * 8 + 2 * (lane & 3);
            *(float2*)(Tout + r0 * 256 + c) = make_float2(acc[mt][nt][0], acc[mt][nt][1]);
            *(float2*)(Tout + (r0 + 8) * 256 + c) = make_float2(acc[mt][nt][2], acc[mt][nt][3]);
            m = fmaxf(m, fmaxf(fmaxf(acc[mt][nt][0], acc[mt][nt][1]),
                               fmaxf(acc[mt][nt][2], acc[mt][nt][3])));
        }
    #pragma unroll
    for (int off = 16; off > 0; off >>= 1)
        m = fmaxf(m, __shfl_xor_sync(0xffffffffu, m, off));
    __shared__ float smax[8];
    if (lane == 0) smax[wid] = m;
    __syncthreads();
    if (tid == 0) {
        float mm = smax[0];
        #pragma unroll
        for (int w = 1; w < 8; w++) mm = fmaxf(mm, smax[w]);
        atomicMax((unsigned int*)&d_maxT[iter], __float_as_uint(mm));
    }
}

// ---------------- sparsemax: Michelot iteration, 1 warp / column ----------
// final A3 recomposed on gathered entries: ((A + s0*T0) + s1*T1) + s2*T2
__global__ void k_sparsemax(float* __restrict__ outw) {
    int colg = (blockIdx.x << 3) + (threadIdx.x >> 5);  // 0..1631
    int lane = threadIdx.x & 31;
    int g = colg / KSEL;
    int jj = colg - g * KSEL;
    int plj = d_perm_local[colg];
    float sdstj = d_sdst[colg];
    const float s0 = 1e-5f / d_maxT[0];
    const float s1 = 1e-5f / d_maxT[1];
    const float s2 = 1e-5f / d_maxT[2];

    float z[7];
    #pragma unroll
    for (int r = 0; r < 7; r++) {
        int i = lane + 32 * r;
        float zz = -1e30f;
        if (i < KSEL) {
            int pli = d_perm_local[g * KSEL + i];
            int64_t idx = ((int64_t)g << 16) + (pli << 8) + plj;
            float a = d_A[idx];
            a = fmaf(s0, d_T0[idx], a);
            a = fmaf(s1, d_T1[idx], a);
            a = fmaf(s2, d_T2[idx], a);
            if (a != 0.0f || i == jj) {
                float raw = d_ssrc[g * KSEL + i] + sdstj;
                float lr = raw > 0.0f ? raw : 0.2f * raw;
                zz = lr + a;   // LAMB = 1
            }
        }
        z[r] = zz;
    }
    float tau = -1e29f;
    int n_prev = 0;
    while (true) {
        float s = 0.0f; int n = 0;
        #pragma unroll
        for (int r = 0; r < 7; r++)
            if (z[r] > tau) { s += z[r]; n++; }
        #pragma unroll
        for (int off = 16; off > 0; off >>= 1) {
            s += __shfl_xor_sync(0xffffffffu, s, off);
            n += __shfl_xor_sync(0xffffffffu, n, off);
        }
        if (n == n_prev) break;
        n_prev = n;
        tau = (s - 1.0f) / (float)n;
    }
    #pragma unroll
    for (int r = 0; r < 7; r++) {
        int i = lane + 32 * r;
        if (i < KSEL) {
            float wv = (z[r] > -1e29f) ? fmaxf(z[r] - tau, 0.0f) : 0.0f;
            outw[(int64_t)(g * KSEL + i) * NK + colg] = wv;
        }
    }
}

// ---------------------------------------------------------------------------
static cudaStream_t get_s2() {
    static cudaStream_t s = [] {
        cudaStream_t t;
        cudaStreamCreateWithFlags(&t, cudaStreamNonBlocking);
        return t;
    }();
    return s;
}
static cudaEvent_t get_ev(int which) {
    static cudaEvent_t e0 = [] {
        cudaEvent_t e; cudaEventCreateWithFlags(&e, cudaEventDisableTiming); return e;
    }();
    static cudaEvent_t e1 = [] {
        cudaEvent_t e; cudaEventCreateWithFlags(&e, cudaEventDisableTiming); return e;
    }();
    return which ? e1 : e0;
}

extern "C" void kernel_launch(void* const* d_in, const int* in_sizes, int n_in,
                              void* d_out, int out_size) {
    const float* feat = (const float*)d_in[0];
    const float* ef   = (const float*)d_in[1];
    const float* att  = (const float*)d_in[2];
    const int*   row  = (const int*)d_in[3];
    const int*   col  = (const int*)d_in[4];
    float* out = (float*)d_out;

    cudaStream_t s2 = get_s2();
    cudaEvent_t evFork = get_ev(0);
    cudaEvent_t evB    = get_ev(1);

    k_init<<<1024, 256>>>(out);
    k_scatter<<<EE/256, 256>>>(ef, row, col);

    // fork: branch B (khop) on s2 — reads d_A, writes d_T0/1/2 + d_maxT
    cudaEventRecord(evFork, 0);
    cudaStreamWaitEvent(s2, evFork, 0);
    for (int it = 0; it < KHOP; it++)
        k_mm<<<dim3(4, 4, BG), 256, 0, s2>>>(it);
    cudaEventRecord(evB, s2);

    // branch A (default stream): agg partials -> score -> topk -> gather
    k_agg_mma<<<dim3(FF/64, NPER/64, BG*4), 256>>>(feat);
    k_score<<<NN/8, 256>>>(feat);
    k_topk<<<BG, 256>>>(out + OUT_PERM_OFF);
    k_gather<<<NK, 128>>>(feat, att, out + OUT_FEATP_OFF);

    // join: sparsemax needs T0/T1/T2+maxT (branch B) + perm/ssrc/sdst (branch A)
    cudaStreamWaitEvent((cudaStream_t)0, evB, 0);
    k_sparsemax<<<NK/8, 256>>>(out + OUT_W_OFF);
}

// round 13
// speedup vs baseline: 1.0844x; 1.0844x over previous
#include <cuda_runtime.h>
#include <cuda_bf16.h>
#include <stdint.h>

#define BG    8      // graphs
#define NPER  256    // nodes per graph
#define NN    2048   // total nodes
#define FF    512    // features
#define EE    65536  // edges
#define KSEL  204    // kept per graph
#define NK    1632   // pooled nodes
#define KHOP  3

#define OUT_FEATP_OFF 0
#define OUT_W_OFF     (NK*FF)                 // 835584
#define OUT_PERM_OFF  (NK*FF + NK*NK)         // 3499008

// tf32 helpers ------------------------------------------------------------
__device__ __forceinline__ uint32_t to_tf32(float x) {
    uint32_t h;
    asm("cvt.rna.tf32.f32 %0, %1;" : "=r"(h) : "f"(x));
    return h;
}
__device__ __forceinline__ void split_tf32(float x, uint32_t& hi, uint32_t& lo) {
    hi = to_tf32(x);
    float l = x - __uint_as_float(hi);
    lo = to_tf32(l);
}
#define MMA8(D,A,B) \
    asm("mma.sync.aligned.m16n8k8.row.col.f32.tf32.tf32.f32 " \
        "{%0,%1,%2,%3},{%4,%5,%6,%7},{%8,%9},{%0,%1,%2,%3};" \
        : "+f"(D[0]), "+f"(D[1]), "+f"(D[2]), "+f"(D[3]) \
        : "r"(A[0]), "r"(A[1]), "r"(A[2]), "r"(A[3]), "r"(B[0]), "r"(B[1]))

// ---------------- scratch (device globals; no allocation allowed) ----------
__device__ float  d_A[BG*NPER*NPER];    // original adjacency (read-only post-scatter)
__device__ float  d_A2[BG*NPER*NPER];   // khop-accumulated adjacency (branch B)
__device__ float  d_T[BG*NPER*NPER];
__device__ float  d_AGG[4*NN*FF];       // 4 k-split partials of agg
__device__ float  d_deg_out[NN];
__device__ float  d_deg_in[NN];
__device__ double d_score[NN];          // double: top-k rank must match truth
__device__ int    d_perm_local[BG*KSEL];
__device__ float  d_ssrc[NK];
__device__ float  d_sdst[NK];
__device__ float  d_maxT[KHOP];

// ---------------- init ---------------------------------------------------
__global__ void k_init(float* out) {
    int64_t i = (int64_t)blockIdx.x * blockDim.x + threadIdx.x;
    int64_t stride = (int64_t)gridDim.x * blockDim.x;
    float* w = out + OUT_W_OFF;
    for (int64_t t = i; t < (int64_t)NK*NK; t += stride) w[t] = 0.0f;
    for (int64_t t = i; t < (int64_t)BG*NPER*NPER; t += stride) d_A[t] = 0.0f;
    for (int64_t t = i; t < NN; t += stride) {
        d_deg_out[t] = 0.0f; d_deg_in[t] = 0.0f;
    }
    if (i < KHOP) d_maxT[i] = 0.0f;
}

// ---------------- scatter edges + degrees --------------------------------
__global__ void k_scatter(const float* __restrict__ ef,
                          const int* __restrict__ row,
                          const int* __restrict__ col) {
    int e = blockIdx.x * blockDim.x + threadIdx.x;
    if (e >= EE) return;
    int r = row[e], c = col[e];
    int g = r >> 8;
    atomicAdd(&d_A[(g << 16) + ((r & 255) << 8) + (c & 255)], ef[e]);
    atomicAdd(&d_deg_out[r], 1.0f);
    atomicAdd(&d_deg_in[c], 1.0f);
}

// ------- partial agg = (sym-norm A^T)[k-quarter] @ feat (3xTF32) ----------
// grid (FF/64, NPER/64, BG*4), block 256. 64x64 tile, warps 2(m)x4(n).
__global__ void __launch_bounds__(256) k_agg_mma(const float* __restrict__ feat) {
    const int g = blockIdx.z >> 2;
    const int split = blockIdx.z & 3;
    const int fBase = blockIdx.x * 64;
    const int cBase = blockIdx.y * 64;
    const int tid = threadIdx.x, lane = tid & 31, wid = tid >> 5;
    const int wm = (wid & 1) * 32, wn = (wid >> 1) * 16;
    __shared__ float As[64][33];   // [m=c_local][k]
    __shared__ float Bs[64][33];   // [n=f_local][k]
    const float* Ag = d_A + (g << 16);
    const float* fg = feat + (g << 17);
    const int splitOff = split * 64;

    float acc[2][2][4] = {};

    const int kl = tid >> 4;          // 0..15
    const int m4 = (tid & 15) * 4;

    for (int s = 0; s < 2; s++) {
        const int kOff = splitOff + s * 32;
        __syncthreads();
        #pragma unroll
        for (int it = 0; it < 2; it++) {
            int k = kl + it * 16;
            int kG = kOff + k;
            float sc = 1.0f / sqrtf(fmaxf(d_deg_out[(g << 8) + kG], 1.0f));
            float4 va = *(const float4*)(Ag + kG * 256 + cBase + m4);
            float4 vb = *(const float4*)(fg + kG * 512 + fBase + m4);
            int c0 = cBase + m4;
            As[m4 + 0][k] = (kG == c0 + 0) ? 0.0f : va.x * sc;
            As[m4 + 1][k] = (kG == c0 + 1) ? 0.0f : va.y * sc;
            As[m4 + 2][k] = (kG == c0 + 2) ? 0.0f : va.z * sc;
            As[m4 + 3][k] = (kG == c0 + 3) ? 0.0f : va.w * sc;
            Bs[m4 + 0][k] = vb.x;
            Bs[m4 + 1][k] = vb.y;
            Bs[m4 + 2][k] = vb.z;
            Bs[m4 + 3][k] = vb.w;
        }
        __syncthreads();
        #pragma unroll
        for (int k8 = 0; k8 < 4; k8++) {
            int kb = k8 * 8;
            uint32_t ah[2][4], al[2][4], bh[2][2], bl[2][2];
            #pragma unroll
            for (int mt = 0; mt < 2; mt++) {
                int r = wm + mt * 16 + (lane >> 2);
                split_tf32(As[r    ][kb + (lane & 3)    ], ah[mt][0], al[mt][0]);
                split_tf32(As[r + 8][kb + (lane & 3)    ], ah[mt][1], al[mt][1]);
                split_tf32(As[r    ][kb + (lane & 3) + 4], ah[mt][2], al[mt][2]);
                split_tf32(As[r + 8][kb + (lane & 3) + 4], ah[mt][3], al[mt][3]);
            }
            #pragma unroll
            for (int nt = 0; nt < 2; nt++) {
                int n = wn + nt * 8 + (lane >> 2);
                split_tf32(Bs[n][kb + (lane & 3)    ], bh[nt][0], bl[nt][0]);
                split_tf32(Bs[n][kb + (lane & 3) + 4], bh[nt][1], bl[nt][1]);
            }
            #pragma unroll
            for (int mt = 0; mt < 2; mt++)
                #pragma unroll
                for (int nt = 0; nt < 2; nt++) {
                    MMA8(acc[mt][nt], al[mt], bh[nt]);
                    MMA8(acc[mt][nt], ah[mt], bl[nt]);
                    MMA8(acc[mt][nt], ah[mt], bh[nt]);
                }
        }
    }
    float* dst = d_AGG + (int64_t)split * NN * FF + ((int64_t)g << 17);
    #pragma unroll
    for (int mt = 0; mt < 2; mt++)
        #pragma unroll
        for (int nt = 0; nt < 2; nt++) {
            int r0 = cBase + wm + mt * 16 + (lane >> 2);
            int c  = fBase + wn + nt * 8 + 2 * (lane & 3);
            *(float2*)(dst + (int64_t)r0 * 512 + c) =
                make_float2(acc[mt][nt][0], acc[mt][nt][1]);
            *(float2*)(dst + (int64_t)(r0 + 8) * 512 + c) =
                make_float2(acc[mt][nt][2], acc[mt][nt][3]);
        }
}

// ------- score[c] = sum_f |feat - dn*(p0+p1+p2+p3)| (double), 1 warp/node -
__global__ void k_score(const float* __restrict__ feat) {
    int w = (blockIdx.x << 3) + (threadIdx.x >> 5);
    int lane = threadIdx.x & 31;
    const float* fr = feat + (int64_t)w * FF;
    const float* p0 = d_AGG + (int64_t)w * FF;
    const float* p1 = p0 + (int64_t)NN * FF;
    const float* p2 = p1 + (int64_t)NN * FF;
    const float* p3 = p2 + (int64_t)NN * FF;
    float dn = 1.0f / sqrtf(fmaxf(d_deg_in[w], 1.0f));
    double p = 0.0;
    #pragma unroll
    for (int it = 0; it < 4; it++) {
        int f = (it * 32 + lane) * 4;
        float4 fv = *(const float4*)(fr + f);
        float4 a0 = *(const float4*)(p0 + f);
        float4 a1 = *(const float4*)(p1 + f);
        float4 a2 = *(const float4*)(p2 + f);
        float4 a3 = *(const float4*)(p3 + f);
        p += (double)fabsf(fv.x - dn * (((a0.x + a1.x) + a2.x) + a3.x))
           + (double)fabsf(fv.y - dn * (((a0.y + a1.y) + a2.y) + a3.y))
           + (double)fabsf(fv.z - dn * (((a0.z + a1.z) + a2.z) + a3.z))
           + (double)fabsf(fv.w - dn * (((a0.w + a1.w) + a2.w) + a3.w));
    }
    #pragma unroll
    for (int off = 16; off > 0; off >>= 1)
        p += __shfl_down_sync(0xffffffffu, p, off);
    if (lane == 0) d_score[w] = p;
}

// ---------------- top-k per graph via bitonic sort (double keys) ----------
__global__ void k_topk(float* __restrict__ out_perm) {
    int g = blockIdx.x;
    int tid = threadIdx.x;
    __shared__ double sk[256];
    __shared__ int    si[256];
    sk[tid] = d_score[g*NPER + tid];
    si[tid] = tid;
    __syncthreads();
    for (int k2 = 2; k2 <= 256; k2 <<= 1) {
        for (int jj = k2 >> 1; jj > 0; jj >>= 1) {
            int ixj = tid ^ jj;
            if (ixj > tid) {
                double a = sk[tid], b = sk[ixj];
                int ia = si[tid], ib = si[ixj];
                bool aFirst = (a > b) || (a == b && ia < ib);
                bool desc = ((tid & k2) == 0);
                bool doswap = desc ? !aFirst : aFirst;
                if (doswap) { sk[tid] = b; sk[ixj] = a; si[tid] = ib; si[ixj] = ia; }
            }
            __syncthreads();
        }
    }
    if (tid < KSEL) {
        d_perm_local[g*KSEL + tid] = si[tid];
        out_perm[g*KSEL + tid] = (float)(g*NPER + si[tid]);
    }
}

// -------------- gather feat_p + attention scores --------------------------
__global__ void k_gather(const float* __restrict__ feat,
                         const float* __restrict__ att,
                         float* __restrict__ out_featp) {
    int i = blockIdx.x;
    int g = i / KSEL;
    int node = g*NPER + d_perm_local[i];
    int tid = threadIdx.x;
    const float* fr = feat + (int64_t)node * FF;
    float* orow = out_featp + (int64_t)i * FF;
    double a1 = 0.0, a2 = 0.0;
    for (int f = tid; f < FF; f += 128) {
        float v = fr[f];
        orow[f] = v;
        a1 += (double)v * (double)att[f];
        a2 += (double)v * (double)att[FF + f];
    }
    #pragma unroll
    for (int off = 16; off > 0; off >>= 1) {
        a1 += __shfl_down_sync(0xffffffffu, a1, off);
        a2 += __shfl_down_sync(0xffffffffu, a2, off);
    }
    __shared__ double s1[4], s2v[4];
    int w = tid >> 5, l = tid & 31;
    if (l == 0) { s1[w] = a1; s2v[w] = a2; }
    __syncthreads();
    if (tid == 0) {
        d_ssrc[i] = (float)(s1[0] + s1[1] + s1[2] + s1[3]);
        d_sdst[i] = (float)(s2v[0] + s2v[1] + s2v[2] + s2v[3]);
    }
}

// ---------------- khop: T = Ain@Ain (tf32) + global max -------------------
// grid (4, 4, BG), block 256. useA selects d_A (iter 0) vs d_A2.
__global__ void __launch_bounds__(256) k_mm(int iter, int useA) {
    const int g = blockIdx.z;
    const int cBase = blockIdx.x * 64;   // n
    const int rBase = blockIdx.y * 64;   // m
    const int tid = threadIdx.x, lane = tid & 31, wid = tid >> 5;
    const int wm = (wid & 1) * 32, wn = (wid >> 1) * 16;
    __shared__ float As[64][36];   // [m][k] (144B row stride: float4-aligned)
    __shared__ float Bs[64][33];   // [n][k]
    const float* Ag = (useA ? d_A : d_A2) + (g << 16);
    float* Tg = d_T + (g << 16);

    float acc[2][2][4] = {};

    const int mA = tid >> 2;                 // 0..63
    const int kA = (tid & 3) * 4;
    const int kB = tid >> 4;                 // 0..15
    const int n4 = (tid & 15) * 4;

    for (int s = 0; s < 8; s++) {
        const int kOff = s * 32;
        __syncthreads();
        #pragma unroll
        for (int it = 0; it < 2; it++) {
            int ka = kA + it * 16;
            float4 va = *(const float4*)(Ag + (rBase + mA) * 256 + kOff + ka);
            *(float4*)&As[mA][ka] = va;
        }
        #pragma unroll
        for (int it = 0; it < 2; it++) {
            int k = kB + it * 16;
            int kG = kOff + k;
            float4 vb = *(const float4*)(Ag + kG * 256 + cBase + n4);
            Bs[n4 + 0][k] = vb.x;
            Bs[n4 + 1][k] = vb.y;
            Bs[n4 + 2][k] = vb.z;
            Bs[n4 + 3][k] = vb.w;
        }
        __syncthreads();
        #pragma unroll
        for (int k8 = 0; k8 < 4; k8++) {
            int kb = k8 * 8;
            uint32_t a[2][4], b[2][2];
            #pragma unroll
            for (int mt = 0; mt < 2; mt++) {
                int r = wm + mt * 16 + (lane >> 2);
                a[mt][0] = to_tf32(As[r    ][kb + (lane & 3)    ]);
                a[mt][1] = to_tf32(As[r + 8][kb + (lane & 3)    ]);
                a[mt][2] = to_tf32(As[r    ][kb + (lane & 3) + 4]);
                a[mt][3] = to_tf32(As[r + 8][kb + (lane & 3) + 4]);
            }
            #pragma unroll
            for (int nt = 0; nt < 2; nt++) {
                int n = wn + nt * 8 + (lane >> 2);
                b[nt][0] = to_tf32(Bs[n][kb + (lane & 3)    ]);
                b[nt][1] = to_tf32(Bs[n][kb + (lane & 3) + 4]);
            }
            #pragma unroll
            for (int mt = 0; mt < 2; mt++)
                #pragma unroll
                for (int nt = 0; nt < 2; nt++)
                    MMA8(acc[mt][nt], a[mt], b[nt]);
        }
    }
    float m = 0.0f;
    #pragma unroll
    for (int mt = 0; mt < 2; mt++)
        #pragma unroll
        for (int nt = 0; nt < 2; nt++) {
            int r0 = rBase + wm + mt * 16 + (lane >> 2);
            int c  = cBase + wn + nt * 8 + 2 * (lane & 3);
            *(float2*)(Tg + r0 * 256 + c) = make_float2(acc[mt][nt][0], acc[mt][nt][1]);
            *(float2*)(Tg + (r0 + 8) * 256 + c) = make_float2(acc[mt][nt][2], acc[mt][nt][3]);
            m = fmaxf(m, fmaxf(fmaxf(acc[mt][nt][0], acc[mt][nt][1]),
                               fmaxf(acc[mt][nt][2], acc[mt][nt][3])));
        }
    #pragma unroll
    for (int off = 16; off > 0; off >>= 1)
        m = fmaxf(m, __shfl_xor_sync(0xffffffffu, m, off));
    __shared__ float smax[8];
    if (lane == 0) smax[wid] = m;
    __syncthreads();
    if (tid == 0) {
        float mm = smax[0];
        #pragma unroll
        for (int w = 1; w < 8; w++) mm = fmaxf(mm, smax[w]);
        atomicMax((unsigned int*)&d_maxT[iter], __float_as_uint(mm));
    }
}

// A2 = (first ? A : A2) + s*T  — exactly one float4 per thread, max MLP
__global__ void k_axpy(int iter, int first) {
    float s = 1e-5f / d_maxT[iter];
    int i = (blockIdx.x << 8) + threadIdx.x;   // 512*256 = 131072 = N/4
    float4 base = first ? ((const float4*)d_A)[i] : ((const float4*)d_A2)[i];
    float4 t = ((const float4*)d_T)[i];
    base.x = fmaf(s, t.x, base.x);
    base.y = fmaf(s, t.y, base.y);
    base.z = fmaf(s, t.z, base.z);
    base.w = fmaf(s, t.w, base.w);
    ((float4*)d_A2)[i] = base;
}

// ---------------- sparsemax: Michelot iteration, 1 warp / column ----------
__global__ void k_sparsemax(float* __restrict__ outw) {
    int colg = (blockIdx.x << 3) + (threadIdx.x >> 5);  // 0..1631
    int lane = threadIdx.x & 31;
    int g = colg / KSEL;
    int jj = colg - g * KSEL;
    int plj = d_perm_local[colg];
    float sdstj = d_sdst[colg];

    float z[7];
    #pragma unroll
    for (int r = 0; r < 7; r++) {
        int i = lane + 32 * r;
        float zz = -1e30f;
        if (i < KSEL) {
            int pli = d_perm_local[g * KSEL + i];
            float a = d_A2[(g << 16) + (pli << 8) + plj];
            if (a != 0.0f || i == jj) {
                float raw = d_ssrc[g * KSEL + i] + sdstj;
                float lr = raw > 0.0f ? raw : 0.2f * raw;
                zz = lr + a;   // LAMB = 1
            }
        }
        z[r] = zz;
    }
    float tau = -1e29f;
    int n_prev = 0;
    while (true) {
        float s = 0.0f; int n = 0;
        #pragma unroll
        for (int r = 0; r < 7; r++)
            if (z[r] > tau) { s += z[r]; n++; }
        #pragma unroll
        for (int off = 16; off > 0; off >>= 1) {
            s += __shfl_xor_sync(0xffffffffu, s, off);
            n += __shfl_xor_sync(0xffffffffu, n, off);
        }
        if (n == n_prev) break;
        n_prev = n;
        tau = (s - 1.0f) / (float)n;
    }
    #pragma unroll
    for (int r = 0; r < 7; r++) {
        int i = lane + 32 * r;
        if (i < KSEL) {
            float wv = (z[r] > -1e29f) ? fmaxf(z[r] - tau, 0.0f) : 0.0f;
            outw[(int64_t)(g * KSEL + i) * NK + colg] = wv;
        }
    }
}

// ---------------------------------------------------------------------------
static cudaStream_t get_s2() {
    static cudaStream_t s = [] {
        cudaStream_t t;
        cudaStreamCreateWithFlags(&t, cudaStreamNonBlocking);
        return t;
    }();
    return s;
}
static cudaEvent_t get_ev(int which) {
    static cudaEvent_t e0 = [] {
        cudaEvent_t e; cudaEventCreateWithFlags(&e, cudaEventDisableTiming); return e;
    }();
    static cudaEvent_t e1 = [] {
        cudaEvent_t e; cudaEventCreateWithFlags(&e, cudaEventDisableTiming); return e;
    }();
    return which ? e1 : e0;
}

extern "C" void kernel_launch(void* const* d_in, const int* in_sizes, int n_in,
                              void* d_out, int out_size) {
    const float* feat = (const float*)d_in[0];
    const float* ef   = (const float*)d_in[1];
    const float* att  = (const float*)d_in[2];
    const int*   row  = (const int*)d_in[3];
    const int*   col  = (const int*)d_in[4];
    float* out = (float*)d_out;

    cudaStream_t s2 = get_s2();
    cudaEvent_t evFork = get_ev(0);
    cudaEvent_t evB    = get_ev(1);

    k_init<<<1024, 256>>>(out);
    k_scatter<<<EE/256, 256>>>(ef, row, col);

    // fork: branch B (khop) on s2 — reads d_A, writes d_T/d_A2/d_maxT
    cudaEventRecord(evFork, 0);
    cudaStreamWaitEvent(s2, evFork, 0);
    for (int it = 0; it < KHOP; it++) {
        k_mm<<<dim3(4, 4, BG), 256, 0, s2>>>(it, it == 0 ? 1 : 0);
        k_axpy<<<512, 256, 0, s2>>>(it, it == 0 ? 1 : 0);
    }
    cudaEventRecord(evB, s2);

    // branch A (default stream): agg partials -> score -> topk -> gather
    k_agg_mma<<<dim3(FF/64, NPER/64, BG*4), 256>>>(feat);
    k_score<<<NN/8, 256>>>(feat);
    k_topk<<<BG, 256>>>(out + OUT_PERM_OFF);
    k_gather<<<NK, 128>>>(feat, att, out + OUT_FEATP_OFF);

    // join: sparsemax needs d_A2 (branch B) + perm/ssrc/sdst (branch A)
    cudaStreamWaitEvent((cudaStream_t)0, evB, 0);
    k_sparsemax<<<NK/8, 256>>>(out + OUT_W_OFF);
}